// round 3
// baseline (speedup 1.0000x reference)
#include <cuda_runtime.h>
#include <math.h>
#include <stdint.h>

#define T_DIM 256
#define N_DIM 1024
#define H_DIM 256
#define L_DIM 16
#define NL_DIM 32
#define C_DIM 64
#define NA_DIM 16
#define ROW_OUT 278
#define G3 768
#define LN (L_DIM*N_DIM)          /* 16384 */
#define TN (T_DIM*N_DIM)          /* 262144 */

// ---------------- scratch (static device memory, no runtime alloc) ----------------
__device__ float g_giF[NL_DIM*G3];
__device__ float g_giB[NL_DIM*G3];
__device__ float g_Hf[2][(size_t)LN*H_DIM];
__device__ float g_Hb[2][(size_t)LN*H_DIM];
__device__ float g_Rproj[(size_t)LN*H_DIM];
__device__ float g_A0[(size_t)TN*H_DIM];
__device__ float g_A1[(size_t)TN*H_DIM];
__device__ float g_GI[(size_t)TN*G3];
__device__ float g_hm[2][N_DIM*H_DIM];
__device__ unsigned g_barc = 0;
__device__ unsigned g_barg = 0;

// ---------------- helpers ----------------
__device__ __forceinline__ uint32_t f2tf(float x){
    uint32_t r; asm("cvt.rna.tf32.f32 %0, %1;" : "=r"(r) : "f"(x)); return r;
}
__device__ __forceinline__ void mma8(float* c, const uint32_t* a, const uint32_t* b){
    asm volatile("mma.sync.aligned.m16n8k8.row.col.f32.tf32.tf32.f32 "
        "{%0,%1,%2,%3},{%4,%5,%6,%7},{%8,%9},{%0,%1,%2,%3};"
        : "+f"(c[0]), "+f"(c[1]), "+f"(c[2]), "+f"(c[3])
        : "r"(a[0]), "r"(a[1]), "r"(a[2]), "r"(a[3]), "r"(b[0]), "r"(b[1]));
}
__device__ __forceinline__ float sigm(float x){ return 1.f/(1.f+expf(-x)); }

__device__ __forceinline__ void grid_sync(unsigned nb){
    __syncthreads();
    if (threadIdx.x == 0){
        volatile unsigned* genp = &g_barg;
        unsigned old = *genp;
        __threadfence();
        if (atomicAdd(&g_barc, 1u) == nb - 1u){
            g_barc = 0u;
            __threadfence();
            *genp = old + 1u;
        } else {
            while (*genp == old) { }
            __threadfence();
        }
    }
    __syncthreads();
}

// ---------------- gi tables: embed @ wih.T + bih  (both directions) ----------------
__global__ void gi_tables(const float* __restrict__ embed,
                          const float* __restrict__ wihF, const float* __restrict__ bihF,
                          const float* __restrict__ wihB, const float* __restrict__ bihB)
{
    int idx = blockIdx.x*blockDim.x + threadIdx.x;
    if (idx >= 2*NL_DIM*G3) return;
    int dir = idx / (NL_DIM*G3);
    int rem = idx % (NL_DIM*G3);
    int e = rem / G3, j = rem % G3;
    const float* wih = dir ? wihB : wihF;
    const float* bih = dir ? bihB : bihF;
    float s = bih[j];
    const float* em = embed + e*H_DIM;
    const float* w  = wih + (size_t)j*H_DIM;
    #pragma unroll 8
    for (int k = 0; k < H_DIM; k++) s += em[k]*w[k];
    (dir ? g_giB : g_giF)[rem] = s;
}

// ---------------- init: zero encoder states, copy h0 ----------------
__global__ void init_state(const float* __restrict__ h0)
{
    size_t stride = (size_t)gridDim.x*blockDim.x;
    size_t i0 = (size_t)blockIdx.x*blockDim.x + threadIdx.x;
    size_t HS = (size_t)LN*H_DIM;
    for (size_t p = i0; p < HS; p += stride){ g_Hf[0][p] = 0.f; g_Hb[0][p] = 0.f; }
    for (size_t p = i0; p < (size_t)N_DIM*H_DIM; p += stride) g_hm[0][p] = h0[p];
}

// ---------------- plain tf32 GEMM (kept for Rproj and layer0) ----------------
// ALOAD: 0 = A param row-major; 1 = concat(Hf0,Hb0) K=512
// EPI:   0 = store; 3 = relu(+bias + Rproj[active] gather)
template<int ALOAD, int EPI>
__global__ void __launch_bounds__(256)
gemm_plain(const float* __restrict__ A, const float* __restrict__ B, int ldb,
           const float* __restrict__ bias, float* __restrict__ out,
           int K, int NC, const int* __restrict__ active)
{
    __shared__ float As[128][20];
    __shared__ float Bs[64][20];
    const int tid = threadIdx.x, lane = tid & 31, wid = tid >> 5;
    const int wm = wid >> 1, wn = wid & 1;
    const int brow = blockIdx.y, bcol = blockIdx.x;
    float acc[2][4][4];
    #pragma unroll
    for (int a = 0; a < 2; a++)
        #pragma unroll
        for (int b = 0; b < 4; b++)
            #pragma unroll
            for (int c = 0; c < 4; c++) acc[a][b][c] = 0.f;

    for (int k0 = 0; k0 < K; k0 += 16){
        #pragma unroll
        for (int i = tid; i < 2048; i += 256){
            int r = i >> 4, c = i & 15;
            int row = brow*128 + r; int k = k0 + c;
            float v;
            if (ALOAD == 0) v = A[(size_t)row*K + k];
            else v = (k < H_DIM) ? g_Hf[0][(size_t)row*H_DIM + k]
                                 : g_Hb[0][(size_t)row*H_DIM + (k - H_DIM)];
            As[r][c] = __uint_as_float(f2tf(v));
        }
        #pragma unroll
        for (int i = tid; i < 1024; i += 256){
            int n = i >> 4, c = i & 15;
            Bs[n][c] = __uint_as_float(f2tf(B[(size_t)(bcol*64 + n)*ldb + k0 + c]));
        }
        __syncthreads();
        #pragma unroll
        for (int kk = 0; kk < 16; kk += 8){
            uint32_t af[2][4], bf[4][2];
            #pragma unroll
            for (int mt = 0; mt < 2; mt++){
                int r0 = wm*32 + mt*16 + (lane >> 2);
                int c0 = kk + (lane & 3);
                af[mt][0] = __float_as_uint(As[r0][c0]);
                af[mt][1] = __float_as_uint(As[r0+8][c0]);
                af[mt][2] = __float_as_uint(As[r0][c0+4]);
                af[mt][3] = __float_as_uint(As[r0+8][c0+4]);
            }
            #pragma unroll
            for (int nt = 0; nt < 4; nt++){
                int n0 = wn*32 + nt*8 + (lane >> 2);
                bf[nt][0] = __float_as_uint(Bs[n0][kk + (lane & 3)]);
                bf[nt][1] = __float_as_uint(Bs[n0][kk + 4 + (lane & 3)]);
            }
            #pragma unroll
            for (int mt = 0; mt < 2; mt++)
                #pragma unroll
                for (int nt = 0; nt < 4; nt++)
                    mma8(acc[mt][nt], af[mt], bf[nt]);
        }
        __syncthreads();
    }
    #pragma unroll
    for (int mt = 0; mt < 2; mt++){
        #pragma unroll
        for (int nt = 0; nt < 4; nt++){
            int rbase = brow*128 + wm*32 + mt*16 + (lane >> 2);
            int cbase = bcol*64 + wn*32 + nt*8 + (lane & 3)*2;
            #pragma unroll
            for (int dr = 0; dr < 2; dr++){
                #pragma unroll
                for (int dc = 0; dc < 2; dc++){
                    int rr = rbase + dr*8, cc = cbase + dc;
                    float v = acc[mt][nt][dr*2 + dc];
                    if (EPI == 3){
                        int n = rr & (N_DIM - 1);
                        int w = active[rr];
                        v += bias[cc];
                        v += g_Rproj[(size_t)(w*N_DIM + n)*H_DIM + cc];
                        v = fmaxf(v, 0.f);
                    }
                    out[(size_t)rr*NC + cc] = v;
                }
            }
        }
    }
}

// ---------------- persistent bidirectional encoder: all 16 steps ----------------
// grid (8, 16) = 128 CTAs x 512 threads. brow<8: fwd over Hf, else bwd over Hb.
// Each CTA: 32 h-cols (x3 gates), 2048 rows (8 chunks of 256).
// Weights resident in SMEM (tf32). A fragments direct from L2 via __ldcg.
#define ENC_SMEM_FLOATS (3*32*260)
#define ENC_SMEM_BYTES (ENC_SMEM_FLOATS*4)

__global__ void __launch_bounds__(512, 1)
enc_persistent(const float* __restrict__ whF, const float* __restrict__ bhF,
               const float* __restrict__ whB, const float* __restrict__ bhB,
               const int* __restrict__ lines)
{
    extern __shared__ float Bs[];      // [3][32][260]
    const int tid = threadIdx.x, lane = tid & 31, wid = tid >> 5;
    const int wm = wid >> 1, wn = wid & 1;      // wm 0..7, wn 0..1
    const int bcol = blockIdx.x;                // 0..7
    const int brow = blockIdx.y;                // 0..15
    const bool dirF = (brow < 8);
    const float* __restrict__ W = dirF ? whF : whB;
    const float* __restrict__ bh = dirF ? bhF : bhB;
    const float* __restrict__ giT = dirF ? g_giF : g_giB;
    const int lrow0 = (dirF ? brow : brow - 8) * 2048;

    // cache weights once (3 gates x 32 cols x 256 k)
    for (int i = tid; i < 3*32*H_DIM; i += 512){
        int g = i >> 13;             // /8192
        int rem = i & 8191;
        int c = rem >> 8, k = rem & 255;
        Bs[(g*32 + c)*260 + k] =
            __uint_as_float(f2tf(W[(size_t)(g*H_DIM + bcol*32 + c)*H_DIM + k]));
    }
    __syncthreads();

    for (int t = 0; t < L_DIM; t++){
        const float* __restrict__ hsrc = dirF ? g_Hf[t & 1] : g_Hb[t & 1];
        float* __restrict__ hdst = dirF ? g_Hf[(t + 1) & 1] : g_Hb[(t + 1) & 1];

        for (int chunk = 0; chunk < 8; chunk++){
            const int r0 = lrow0 + chunk*256 + wm*32;
            float acc[3][2][2][4];
            #pragma unroll
            for (int g = 0; g < 3; g++)
                #pragma unroll
                for (int a = 0; a < 2; a++)
                    #pragma unroll
                    for (int b = 0; b < 2; b++)
                        #pragma unroll
                        for (int c = 0; c < 4; c++) acc[g][a][b][c] = 0.f;

            #pragma unroll 2
            for (int k0 = 0; k0 < H_DIM; k0 += 8){
                uint32_t af[2][4];
                #pragma unroll
                for (int mt = 0; mt < 2; mt++){
                    const float* p = hsrc + (size_t)(r0 + mt*16 + (lane >> 2))*H_DIM
                                          + k0 + (lane & 3);
                    af[mt][0] = f2tf(__ldcg(p));
                    af[mt][1] = f2tf(__ldcg(p + 8*H_DIM));
                    af[mt][2] = f2tf(__ldcg(p + 4));
                    af[mt][3] = f2tf(__ldcg(p + 8*H_DIM + 4));
                }
                uint32_t bf[3][2][2];
                #pragma unroll
                for (int g = 0; g < 3; g++)
                    #pragma unroll
                    for (int nt = 0; nt < 2; nt++){
                        int n0 = wn*16 + nt*8 + (lane >> 2);
                        bf[g][nt][0] = __float_as_uint(Bs[(g*32 + n0)*260 + k0 + (lane & 3)]);
                        bf[g][nt][1] = __float_as_uint(Bs[(g*32 + n0)*260 + k0 + 4 + (lane & 3)]);
                    }
                #pragma unroll
                for (int g = 0; g < 3; g++)
                    #pragma unroll
                    for (int mt = 0; mt < 2; mt++)
                        #pragma unroll
                        for (int nt = 0; nt < 2; nt++)
                            mma8(acc[g][mt][nt], af[mt], bf[g][nt]);
            }

            // epilogue: gates
            #pragma unroll
            for (int mt = 0; mt < 2; mt++){
                #pragma unroll
                for (int nt = 0; nt < 2; nt++){
                    #pragma unroll
                    for (int dr = 0; dr < 2; dr++){
                        int lr = r0 + mt*16 + (lane >> 2) + dr*8;   // 0..16383
                        int iroll = lr >> 10;
                        int nb = lr & (N_DIM - 1);
                        int l = dirF ? ((iroll + t) & 15) : ((iroll + 15 - t) & 15);
                        const float* gi = giT + lines[nb*L_DIM + l]*G3;
                        #pragma unroll
                        for (int dc = 0; dc < 2; dc++){
                            int hc = bcol*32 + wn*16 + nt*8 + (lane & 3)*2 + dc;
                            float gr = acc[0][mt][nt][dr*2+dc] + bh[hc];
                            float gz = acc[1][mt][nt][dr*2+dc] + bh[H_DIM + hc];
                            float gn = acc[2][mt][nt][dr*2+dc] + bh[2*H_DIM + hc];
                            float r  = sigm(gi[hc] + gr);
                            float z  = sigm(gi[H_DIM + hc] + gz);
                            float nn = tanhf(gi[2*H_DIM + hc] + r*gn);
                            float hold = __ldcg(&hsrc[(size_t)lr*H_DIM + hc]);
                            float hnew = (1.f - z)*nn + z*hold;
                            __stcg(&hdst[(size_t)lr*H_DIM + hc], hnew);
                        }
                    }
                }
            }
        }
        grid_sync(128);
    }
}

// ---------------- feed-forward GEMM: resident weights, direct-LDG A frags ----------
// out[M,NC] = op(A[M,256] @ W[NC,256]^T + bias). NTN = n-tiles per warp (4 or 8).
// BN = NTN*16 cols per CTA. grid.x = NC/BN coltiles; grid.y CTAs loop row-tiles.
// EPI: 1 = relu(+bias), 2 = +bias
template<int NTN, int EPI>
__global__ void __launch_bounds__(256, (NTN == 4) ? 2 : 1)
gemm_ff(const float* __restrict__ A, const float* __restrict__ W,
        const float* __restrict__ bias, float* __restrict__ out,
        int NC, int nrow_tiles)
{
    constexpr int BN = NTN*16;
    extern __shared__ float Bs[];       // [BN][260]
    const int tid = threadIdx.x, lane = tid & 31, wid = tid >> 5;
    const int wm = wid >> 1, wn = wid & 1;
    const int bcol = blockIdx.x;

    for (int i = tid; i < BN*H_DIM; i += 256){
        int c = i >> 8, k = i & 255;
        Bs[c*260 + k] =
            __uint_as_float(f2tf(W[(size_t)(bcol*BN + c)*H_DIM + k]));
    }
    __syncthreads();

    for (int rt = blockIdx.y; rt < nrow_tiles; rt += gridDim.y){
        const int r0 = rt*128 + wm*32;
        float acc[2][NTN][4];
        #pragma unroll
        for (int a = 0; a < 2; a++)
            #pragma unroll
            for (int b = 0; b < NTN; b++)
                #pragma unroll
                for (int c = 0; c < 4; c++) acc[a][b][c] = 0.f;

        #pragma unroll 2
        for (int k0 = 0; k0 < H_DIM; k0 += 8){
            uint32_t af[2][4];
            #pragma unroll
            for (int mt = 0; mt < 2; mt++){
                const float* p = A + (size_t)(r0 + mt*16 + (lane >> 2))*H_DIM
                                   + k0 + (lane & 3);
                af[mt][0] = f2tf(__ldg(p));
                af[mt][1] = f2tf(__ldg(p + 8*H_DIM));
                af[mt][2] = f2tf(__ldg(p + 4));
                af[mt][3] = f2tf(__ldg(p + 8*H_DIM + 4));
            }
            uint32_t bf[NTN][2];
            #pragma unroll
            for (int nt = 0; nt < NTN; nt++){
                int n0 = wn*NTN*8 + nt*8 + (lane >> 2);
                bf[nt][0] = __float_as_uint(Bs[n0*260 + k0 + (lane & 3)]);
                bf[nt][1] = __float_as_uint(Bs[n0*260 + k0 + 4 + (lane & 3)]);
            }
            #pragma unroll
            for (int mt = 0; mt < 2; mt++)
                #pragma unroll
                for (int nt = 0; nt < NTN; nt++)
                    mma8(acc[mt][nt], af[mt], bf[nt]);
        }

        #pragma unroll
        for (int mt = 0; mt < 2; mt++){
            #pragma unroll
            for (int nt = 0; nt < NTN; nt++){
                #pragma unroll
                for (int dr = 0; dr < 2; dr++){
                    int rr = rt*128 + wm*32 + mt*16 + (lane >> 2) + dr*8;
                    #pragma unroll
                    for (int dc = 0; dc < 2; dc++){
                        int cc = bcol*BN + wn*NTN*8 + nt*8 + (lane & 3)*2 + dc;
                        float v = acc[mt][nt][dr*2 + dc] + bias[cc];
                        if (EPI == 1) v = fmaxf(v, 0.f);
                        out[(size_t)rr*NC + cc] = v;
                    }
                }
            }
        }
    }
}

// ---------------- persistent main-loop GRU v2: direct-LDG A frags ----------------
// grid (16, 8) = 128 CTAs x 256 threads. Weights resident; no SMEM staging for A.
#define MAIN_SMEM_FLOATS (3*16*260)
#define MAIN_SMEM_BYTES (MAIN_SMEM_FLOATS*4)

__global__ void __launch_bounds__(256, 1)
main_gru_v2(const float* __restrict__ whh, const float* __restrict__ bhh,
            float* __restrict__ out)
{
    extern __shared__ float Bs[];      // [3][16][260]
    const int tid = threadIdx.x, lane = tid & 31, wid = tid >> 5;
    const int wm = wid >> 1, wn = wid & 1;
    const int bcol = blockIdx.x;       // 0..15
    const int row0 = blockIdx.y*128 + wm*32;

    for (int i = tid; i < 3*16*H_DIM; i += 256){
        int g = i >> 12;
        int rem = i & 4095;
        int c = rem >> 8, k = rem & 255;
        Bs[(g*16 + c)*260 + k] =
            __uint_as_float(f2tf(whh[(size_t)(g*H_DIM + bcol*16 + c)*H_DIM + k]));
    }
    const int cb0 = bcol*16 + wn*8 + (lane & 3)*2;
    float bR0 = bhh[cb0],           bR1 = bhh[cb0 + 1];
    float bZ0 = bhh[H_DIM + cb0],   bZ1 = bhh[H_DIM + cb0 + 1];
    float bN0 = bhh[2*H_DIM + cb0], bN1 = bhh[2*H_DIM + cb0 + 1];
    __syncthreads();

    for (int t = 0; t < T_DIM; t++){
        const float* __restrict__ hsrc = g_hm[t & 1];
        float* __restrict__ hdst = g_hm[(t + 1) & 1];

        float acc[3][2][4];
        #pragma unroll
        for (int g = 0; g < 3; g++)
            #pragma unroll
            for (int m = 0; m < 2; m++)
                #pragma unroll
                for (int c = 0; c < 4; c++) acc[g][m][c] = 0.f;

        #pragma unroll 4
        for (int k0 = 0; k0 < H_DIM; k0 += 8){
            uint32_t af[2][4];
            #pragma unroll
            for (int mt = 0; mt < 2; mt++){
                const float* p = hsrc + (size_t)(row0 + mt*16 + (lane >> 2))*H_DIM
                                      + k0 + (lane & 3);
                af[mt][0] = f2tf(__ldcg(p));
                af[mt][1] = f2tf(__ldcg(p + 8*H_DIM));
                af[mt][2] = f2tf(__ldcg(p + 4));
                af[mt][3] = f2tf(__ldcg(p + 8*H_DIM + 4));
            }
            uint32_t bf[3][2];
            int n0 = wn*8 + (lane >> 2);
            #pragma unroll
            for (int g = 0; g < 3; g++){
                bf[g][0] = __float_as_uint(Bs[(g*16 + n0)*260 + k0 + (lane & 3)]);
                bf[g][1] = __float_as_uint(Bs[(g*16 + n0)*260 + k0 + 4 + (lane & 3)]);
            }
            #pragma unroll
            for (int g = 0; g < 3; g++)
                #pragma unroll
                for (int mt = 0; mt < 2; mt++)
                    mma8(acc[g][mt], af[mt], bf[g]);
        }

        const float* __restrict__ gi_t = g_GI + (size_t)t*N_DIM*G3;
        float* __restrict__ out_t = out + ((size_t)t*N_DIM)*ROW_OUT;
        #pragma unroll
        for (int mt = 0; mt < 2; mt++){
            #pragma unroll
            for (int dr = 0; dr < 2; dr++){
                int row = row0 + mt*16 + (lane >> 2) + dr*8;
                const float* gi = gi_t + (size_t)row*G3;
                #pragma unroll
                for (int dc = 0; dc < 2; dc++){
                    int c = cb0 + dc;
                    float gr = acc[0][mt][dr*2+dc] + (dc ? bR1 : bR0);
                    float gz = acc[1][mt][dr*2+dc] + (dc ? bZ1 : bZ0);
                    float gn = acc[2][mt][dr*2+dc] + (dc ? bN1 : bN0);
                    float r  = sigm(gi[c] + gr);
                    float z  = sigm(gi[H_DIM + c] + gz);
                    float nn = tanhf(gi[2*H_DIM + c] + r*gn);
                    float hold = __ldcg(&hsrc[(size_t)row*H_DIM + c]);
                    float hnew = (1.f - z)*nn + z*hold;
                    __stcg(&hdst[(size_t)row*H_DIM + c], hnew);
                    out_t[(size_t)row*ROW_OUT + 4 + c] = hnew;
                }
            }
        }
        grid_sync(128);
    }
}

// ---------------- heads: softmax(actor), critic, scalar fields ----------------
__global__ void __launch_bounds__(256)
heads_kernel(float* __restrict__ out, const int* __restrict__ actions,
             const int* __restrict__ active, const float* __restrict__ p0,
             const float* __restrict__ pp0,
             const float* __restrict__ w_actor, const float* __restrict__ b_actor,
             const float* __restrict__ w_critic, const float* __restrict__ b_critic)
{
    int wid = threadIdx.x >> 5, lane = threadIdx.x & 31;
    size_t row = (size_t)blockIdx.x*8 + wid;
    float* orow = out + row*ROW_OUT;
    float hv[8];
    #pragma unroll
    for (int i = 0; i < 8; i++) hv[i] = orow[4 + lane + 32*i];

    float lg = 0.f;
    #pragma unroll
    for (int a = 0; a < NA_DIM; a++){
        float s = 0.f;
        #pragma unroll
        for (int i = 0; i < 8; i++) s += hv[i]*w_actor[a*H_DIM + lane + 32*i];
        #pragma unroll
        for (int o = 16; o > 0; o >>= 1) s += __shfl_xor_sync(0xffffffffu, s, o);
        if (lane == a) lg = s + b_actor[a];
    }
    float m = (lane < NA_DIM) ? lg : -1e30f;
    #pragma unroll
    for (int o = 16; o > 0; o >>= 1) m = fmaxf(m, __shfl_xor_sync(0xffffffffu, m, o));
    float e = (lane < NA_DIM) ? expf(lg - m) : 0.f;
    float den = e;
    #pragma unroll
    for (int o = 16; o > 0; o >>= 1) den += __shfl_xor_sync(0xffffffffu, den, o);
    if (lane < NA_DIM) orow[260 + lane] = e/den;

    float s = 0.f;
    #pragma unroll
    for (int i = 0; i < 8; i++) s += hv[i]*w_critic[lane + 32*i];
    #pragma unroll
    for (int o = 16; o > 0; o >>= 1) s += __shfl_xor_sync(0xffffffffu, s, o);

    int n = (int)(row & (N_DIM - 1));
    if (lane == 0)  orow[3]   = s + b_critic[0];
    if (lane == 16) orow[0]   = (float)actions[row];
    if (lane == 17) orow[1]   = p0[n];
    if (lane == 18) orow[2]   = (float)active[row];
    if (lane == 19) orow[276] = pp0[n*2];
    if (lane == 20) orow[277] = pp0[n*2 + 1];
}

// ---------------- launch ----------------
extern "C" void kernel_launch(void* const* d_in, const int* in_sizes, int n_in,
                              void* d_out, int out_size)
{
    (void)in_sizes; (void)n_in; (void)out_size;
    const float* condition = (const float*)d_in[0];
    const int*   active    = (const int*)d_in[1];
    const int*   lines     = (const int*)d_in[2];
    const int*   actions   = (const int*)d_in[3];
    const float* h0        = (const float*)d_in[4];
    const float* p0        = (const float*)d_in[5];
    const float* pp0       = (const float*)d_in[6];
    const float* embed     = (const float*)d_in[7];
    const float* wih_f = (const float*)d_in[8],  *whh_f = (const float*)d_in[9];
    const float* bih_f = (const float*)d_in[10], *bhh_f = (const float*)d_in[11];
    const float* wih_b = (const float*)d_in[12], *whh_b = (const float*)d_in[13];
    const float* bih_b = (const float*)d_in[14], *bhh_b = (const float*)d_in[15];
    const float* f_w0 = (const float*)d_in[16], *f_b0 = (const float*)d_in[17];
    const float* f_w1 = (const float*)d_in[18], *f_b1 = (const float*)d_in[19];
    const float* f_w2 = (const float*)d_in[20], *f_b2 = (const float*)d_in[21];
    const float* c_wih = (const float*)d_in[22], *c_whh = (const float*)d_in[23];
    const float* c_bih = (const float*)d_in[24], *c_bhh = (const float*)d_in[25];
    const float* w_critic = (const float*)d_in[26], *b_critic = (const float*)d_in[27];
    const float* w_actor  = (const float*)d_in[28], *b_actor  = (const float*)d_in[29];
    float* out = (float*)d_out;

    float *A0p, *A1p, *Rp, *GIp;
    cudaGetSymbolAddress((void**)&A0p, g_A0);
    cudaGetSymbolAddress((void**)&A1p, g_A1);
    cudaGetSymbolAddress((void**)&Rp,  g_Rproj);
    cudaGetSymbolAddress((void**)&GIp, g_GI);

    static int attr_done = 0;
    cudaFuncSetAttribute(enc_persistent,
                         cudaFuncAttributeMaxDynamicSharedMemorySize, ENC_SMEM_BYTES);
    cudaFuncSetAttribute(main_gru_v2,
                         cudaFuncAttributeMaxDynamicSharedMemorySize, MAIN_SMEM_BYTES);
    cudaFuncSetAttribute(gemm_ff<4,1>,
                         cudaFuncAttributeMaxDynamicSharedMemorySize, 64*260*4);
    cudaFuncSetAttribute(gemm_ff<8,2>,
                         cudaFuncAttributeMaxDynamicSharedMemorySize, 128*260*4);
    (void)attr_done;

    // 0) gi lookup tables + state init
    gi_tables<<<(2*NL_DIM*G3 + 255)/256, 256>>>(embed, wih_f, bih_f, wih_b, bih_b);
    init_state<<<4096, 256>>>(h0);

    // 1) persistent bidirectional encoder (16 steps, one kernel)
    enc_persistent<<<dim3(8, 16), 512, ENC_SMEM_BYTES>>>(whh_f, bhh_f, whh_b, bhh_b, lines);

    // 2) Rproj = Hmem @ W0r^T  (dedup over (w,n))
    gemm_plain<1, 0><<<dim3(4, 128), 256>>>(nullptr, f_w0 + 64, 576, nullptr, Rp, 512, 256, nullptr);
    // 3) A0 = relu(cond @ W0c^T + Rproj[active] + b0)
    gemm_plain<0, 3><<<dim3(4, 2048), 256>>>(condition, f_w0, 576, f_b0, A0p, 64, 256, active);
    // 4) A1 = relu(A0 @ w1^T + b1); A0 = relu(A1 @ w2^T + b2)
    gemm_ff<4, 1><<<dim3(4, 64), 256, 64*260*4>>>(A0p, f_w1, f_b1, A1p, 256, 2048);
    gemm_ff<4, 1><<<dim3(4, 64), 256, 64*260*4>>>(A1p, f_w2, f_b2, A0p, 256, 2048);
    // 5) GI = A0 @ c_wih^T + c_bih
    gemm_ff<8, 2><<<dim3(6, 24), 256, 128*260*4>>>(A0p, c_wih, c_bih, GIp, 768, 2048);

    // 6) persistent main GRU (256 steps, one kernel)
    main_gru_v2<<<dim3(16, 8), 256, MAIN_SMEM_BYTES>>>(c_whh, c_bhh, out);

    // 7) heads + scalar output fields
    heads_kernel<<<TN/8, 256>>>(out, actions, active, p0, pp0,
                                w_actor, b_actor, w_critic, b_critic);
}

// round 4
// speedup vs baseline: 1.3356x; 1.3356x over previous
#include <cuda_runtime.h>
#include <math.h>
#include <stdint.h>

#define T_DIM 256
#define N_DIM 1024
#define H_DIM 256
#define L_DIM 16
#define NL_DIM 32
#define C_DIM 64
#define NA_DIM 16
#define ROW_OUT 278
#define G3 768
#define LN (L_DIM*N_DIM)          /* 16384 */
#define TN (T_DIM*N_DIM)          /* 262144 */

// ---------------- scratch ----------------
__device__ float g_giF[NL_DIM*G3];
__device__ float g_giB[NL_DIM*G3];
__device__ float g_Hf[2][(size_t)LN*H_DIM];
__device__ float g_Hb[2][(size_t)LN*H_DIM];
__device__ float g_Rproj[(size_t)LN*H_DIM];
__device__ float g_A0[(size_t)TN*H_DIM];
__device__ float g_A1[(size_t)TN*H_DIM];
__device__ float g_GI[(size_t)TN*G3];
__device__ float g_hm[2][N_DIM*H_DIM];
__device__ unsigned g_barc = 0;
__device__ unsigned g_barg = 0;

// ---------------- helpers ----------------
__device__ __forceinline__ uint32_t f2tf(float x){
    uint32_t r; asm("cvt.rna.tf32.f32 %0, %1;" : "=r"(r) : "f"(x)); return r;
}
__device__ __forceinline__ void mma8(float* c, const uint32_t* a, const uint32_t* b){
    asm volatile("mma.sync.aligned.m16n8k8.row.col.f32.tf32.tf32.f32 "
        "{%0,%1,%2,%3},{%4,%5,%6,%7},{%8,%9},{%0,%1,%2,%3};"
        : "+f"(c[0]), "+f"(c[1]), "+f"(c[2]), "+f"(c[3])
        : "r"(a[0]), "r"(a[1]), "r"(a[2]), "r"(a[3]), "r"(b[0]), "r"(b[1]));
}
__device__ __forceinline__ float sigm(float x){ return 1.f/(1.f+expf(-x)); }
__device__ __forceinline__ void cp16(void* smem_dst, const void* gsrc){
    uint32_t s = (uint32_t)__cvta_generic_to_shared(smem_dst);
    asm volatile("cp.async.cg.shared.global [%0], [%1], 16;" :: "r"(s), "l"(gsrc));
}
__device__ __forceinline__ void cp_commit(){ asm volatile("cp.async.commit_group;"); }
template<int N> __device__ __forceinline__ void cp_wait(){
    asm volatile("cp.async.wait_group %0;" :: "n"(N));
}

__device__ __forceinline__ void grid_sync(unsigned nb){
    __syncthreads();
    if (threadIdx.x == 0){
        volatile unsigned* genp = &g_barg;
        unsigned old = *genp;
        __threadfence();
        if (atomicAdd(&g_barc, 1u) == nb - 1u){
            g_barc = 0u;
            __threadfence();
            *genp = old + 1u;
        } else {
            while (*genp == old) { }
            __threadfence();
        }
    }
    __syncthreads();
}

// ---------------- gi tables ----------------
__global__ void gi_tables(const float* __restrict__ embed,
                          const float* __restrict__ wihF, const float* __restrict__ bihF,
                          const float* __restrict__ wihB, const float* __restrict__ bihB)
{
    int idx = blockIdx.x*blockDim.x + threadIdx.x;
    if (idx >= 2*NL_DIM*G3) return;
    int dir = idx / (NL_DIM*G3);
    int rem = idx % (NL_DIM*G3);
    int e = rem / G3, j = rem % G3;
    const float* wih = dir ? wihB : wihF;
    const float* bih = dir ? bihB : bihF;
    float s = bih[j];
    const float* em = embed + e*H_DIM;
    const float* w  = wih + (size_t)j*H_DIM;
    #pragma unroll 8
    for (int k = 0; k < H_DIM; k++) s += em[k]*w[k];
    (dir ? g_giB : g_giF)[rem] = s;
}

// ---------------- init ----------------
__global__ void init_state(const float* __restrict__ h0)
{
    size_t stride = (size_t)gridDim.x*blockDim.x;
    size_t i0 = (size_t)blockIdx.x*blockDim.x + threadIdx.x;
    size_t HS = (size_t)LN*H_DIM;
    for (size_t p = i0; p < HS; p += stride){ g_Hf[0][p] = 0.f; g_Hb[0][p] = 0.f; }
    for (size_t p = i0; p < (size_t)N_DIM*H_DIM; p += stride) g_hm[0][p] = h0[p];
}

// ---------------- plain tf32 GEMM (Rproj + layer0) ----------------
template<int ALOAD, int EPI>
__global__ void __launch_bounds__(256)
gemm_plain(const float* __restrict__ A, const float* __restrict__ B, int ldb,
           const float* __restrict__ bias, float* __restrict__ out,
           int K, int NC, const int* __restrict__ active)
{
    __shared__ float As[128][20];
    __shared__ float Bs[64][20];
    const int tid = threadIdx.x, lane = tid & 31, wid = tid >> 5;
    const int wm = wid >> 1, wn = wid & 1;
    const int brow = blockIdx.y, bcol = blockIdx.x;
    float acc[2][4][4];
    #pragma unroll
    for (int a = 0; a < 2; a++)
        #pragma unroll
        for (int b = 0; b < 4; b++)
            #pragma unroll
            for (int c = 0; c < 4; c++) acc[a][b][c] = 0.f;

    for (int k0 = 0; k0 < K; k0 += 16){
        #pragma unroll
        for (int i = tid; i < 2048; i += 256){
            int r = i >> 4, c = i & 15;
            int row = brow*128 + r; int k = k0 + c;
            float v;
            if (ALOAD == 0) v = A[(size_t)row*K + k];
            else v = (k < H_DIM) ? g_Hf[0][(size_t)row*H_DIM + k]
                                 : g_Hb[0][(size_t)row*H_DIM + (k - H_DIM)];
            As[r][c] = __uint_as_float(f2tf(v));
        }
        #pragma unroll
        for (int i = tid; i < 1024; i += 256){
            int n = i >> 4, c = i & 15;
            Bs[n][c] = __uint_as_float(f2tf(B[(size_t)(bcol*64 + n)*ldb + k0 + c]));
        }
        __syncthreads();
        #pragma unroll
        for (int kk = 0; kk < 16; kk += 8){
            uint32_t af[2][4], bf[4][2];
            #pragma unroll
            for (int mt = 0; mt < 2; mt++){
                int r0 = wm*32 + mt*16 + (lane >> 2);
                int c0 = kk + (lane & 3);
                af[mt][0] = __float_as_uint(As[r0][c0]);
                af[mt][1] = __float_as_uint(As[r0+8][c0]);
                af[mt][2] = __float_as_uint(As[r0][c0+4]);
                af[mt][3] = __float_as_uint(As[r0+8][c0+4]);
            }
            #pragma unroll
            for (int nt = 0; nt < 4; nt++){
                int n0 = wn*32 + nt*8 + (lane >> 2);
                bf[nt][0] = __float_as_uint(Bs[n0][kk + (lane & 3)]);
                bf[nt][1] = __float_as_uint(Bs[n0][kk + 4 + (lane & 3)]);
            }
            #pragma unroll
            for (int mt = 0; mt < 2; mt++)
                #pragma unroll
                for (int nt = 0; nt < 4; nt++)
                    mma8(acc[mt][nt], af[mt], bf[nt]);
        }
        __syncthreads();
    }
    #pragma unroll
    for (int mt = 0; mt < 2; mt++){
        #pragma unroll
        for (int nt = 0; nt < 4; nt++){
            int rbase = brow*128 + wm*32 + mt*16 + (lane >> 2);
            int cbase = bcol*64 + wn*32 + nt*8 + (lane & 3)*2;
            #pragma unroll
            for (int dr = 0; dr < 2; dr++){
                #pragma unroll
                for (int dc = 0; dc < 2; dc++){
                    int rr = rbase + dr*8, cc = cbase + dc;
                    float v = acc[mt][nt][dr*2 + dc];
                    if (EPI == 3){
                        int n = rr & (N_DIM - 1);
                        int w = active[rr];
                        v += bias[cc];
                        v += g_Rproj[(size_t)(w*N_DIM + n)*H_DIM + cc];
                        v = fmaxf(v, 0.f);
                    }
                    out[(size_t)rr*NC + cc] = v;
                }
            }
        }
    }
}

// ---------------- persistent encoder v2: resident weights + cp.async pipeline ------
// grid (8 bcol, 16 slab) = 128 CTAs x 512 thr. slab<8: fwd (Hf), else bwd (Hb).
// CTA: 32 h-cols x 3 gates, 2048 rows in 8 chunks of 256; K-chunk 32 double-buffered.
#define ENC_W_FLOATS (3*32*260)            /* 24960 */
#define ENC_A_FLOATS (2*256*36)            /* 18432 */
#define ENC_SMEM_BYTES ((ENC_W_FLOATS + ENC_A_FLOATS)*4)

__global__ void __launch_bounds__(512, 1)
enc_v2(const float* __restrict__ whF, const float* __restrict__ bhF,
       const float* __restrict__ whB, const float* __restrict__ bhB,
       const int* __restrict__ lines)
{
    extern __shared__ float sm[];
    float* Ws = sm;
    float* As = sm + ENC_W_FLOATS;
    const int tid = threadIdx.x, lane = tid & 31, wid = tid >> 5;
    const int wm = wid >> 1, wn = wid & 1;      // wm 0..7, wn 0..1
    const int bcol = blockIdx.x;                // 0..7
    const int slab = blockIdx.y;                // 0..15
    const bool dirF = (slab < 8);
    const float* __restrict__ W  = dirF ? whF : whB;
    const float* __restrict__ bh = dirF ? bhF : bhB;
    const float* __restrict__ giT = dirF ? g_giF : g_giB;
    const int lrow0 = (dirF ? slab : slab - 8) * 2048;

    for (int i = tid; i < 3*32*H_DIM; i += 512){
        int g = i >> 13, rem = i & 8191;
        int c = rem >> 8, k = rem & 255;
        Ws[(g*32 + c)*260 + k] =
            __uint_as_float(f2tf(W[(size_t)(g*H_DIM + bcol*32 + c)*H_DIM + k]));
    }
    __syncthreads();

    for (int t = 0; t < L_DIM; t++){
        const float* __restrict__ hsrc = dirF ? g_Hf[t & 1] : g_Hb[t & 1];
        float* __restrict__ hdst = dirF ? g_Hf[(t + 1) & 1] : g_Hb[(t + 1) & 1];

        auto stage = [&](int p){
            int chunk = p >> 3, kb = p & 7, buf = p & 1;
            const float* src = hsrc + (size_t)(lrow0 + chunk*256)*H_DIM + kb*32;
            float* dst = As + buf*256*36;
            #pragma unroll
            for (int i = tid; i < 2048; i += 512){
                int r = i >> 3, q = (i & 7)*4;
                cp16(&dst[r*36 + q], src + (size_t)r*H_DIM + q);
            }
            cp_commit();
        };

        float acc[3][2][2][4];
        stage(0);
        for (int p = 0; p < 64; p++){
            if (p + 1 < 64){ stage(p + 1); cp_wait<1>(); }
            else cp_wait<0>();
            __syncthreads();
            const int kb = p & 7;
            if (kb == 0){
                #pragma unroll
                for (int g = 0; g < 3; g++)
                    #pragma unroll
                    for (int a = 0; a < 2; a++)
                        #pragma unroll
                        for (int b = 0; b < 2; b++)
                            #pragma unroll
                            for (int c = 0; c < 4; c++) acc[g][a][b][c] = 0.f;
            }
            const float* Ab = As + (p & 1)*256*36;
            const int kbase = kb*32;
            #pragma unroll
            for (int kk = 0; kk < 32; kk += 8){
                uint32_t af[2][4];
                #pragma unroll
                for (int mt = 0; mt < 2; mt++){
                    int r0 = wm*32 + mt*16 + (lane >> 2);
                    int c0 = kk + (lane & 3);
                    af[mt][0] = f2tf(Ab[r0*36 + c0]);
                    af[mt][1] = f2tf(Ab[(r0+8)*36 + c0]);
                    af[mt][2] = f2tf(Ab[r0*36 + c0 + 4]);
                    af[mt][3] = f2tf(Ab[(r0+8)*36 + c0 + 4]);
                }
                uint32_t bf[3][2][2];
                #pragma unroll
                for (int g = 0; g < 3; g++)
                    #pragma unroll
                    for (int nt = 0; nt < 2; nt++){
                        int n0 = wn*16 + nt*8 + (lane >> 2);
                        bf[g][nt][0] = __float_as_uint(Ws[(g*32 + n0)*260 + kbase + kk + (lane & 3)]);
                        bf[g][nt][1] = __float_as_uint(Ws[(g*32 + n0)*260 + kbase + kk + 4 + (lane & 3)]);
                    }
                #pragma unroll
                for (int g = 0; g < 3; g++)
                    #pragma unroll
                    for (int mt = 0; mt < 2; mt++)
                        #pragma unroll
                        for (int nt = 0; nt < 2; nt++)
                            mma8(acc[g][mt][nt], af[mt], bf[g][nt]);
            }
            __syncthreads();

            if (kb == 7){
                const int base = lrow0 + (p >> 3)*256;
                #pragma unroll
                for (int mt = 0; mt < 2; mt++){
                    #pragma unroll
                    for (int nt = 0; nt < 2; nt++){
                        #pragma unroll
                        for (int dr = 0; dr < 2; dr++){
                            int lr = base + wm*32 + mt*16 + (lane >> 2) + dr*8;
                            int iroll = lr >> 10;
                            int nb = lr & (N_DIM - 1);
                            int l = dirF ? ((iroll + t) & 15) : ((iroll + 15 - t) & 15);
                            const float* gi = giT + __ldg(&lines[nb*L_DIM + l])*G3;
                            #pragma unroll
                            for (int dc = 0; dc < 2; dc++){
                                int hc = bcol*32 + wn*16 + nt*8 + (lane & 3)*2 + dc;
                                float gr = acc[0][mt][nt][dr*2+dc] + bh[hc];
                                float gz = acc[1][mt][nt][dr*2+dc] + bh[H_DIM + hc];
                                float gn = acc[2][mt][nt][dr*2+dc] + bh[2*H_DIM + hc];
                                float r  = sigm(__ldg(&gi[hc]) + gr);
                                float z  = sigm(__ldg(&gi[H_DIM + hc]) + gz);
                                float nn = tanhf(__ldg(&gi[2*H_DIM + hc]) + r*gn);
                                float hold = __ldcg(&hsrc[(size_t)lr*H_DIM + hc]);
                                float hnew = (1.f - z)*nn + z*hold;
                                __stcg(&hdst[(size_t)lr*H_DIM + hc], hnew);
                            }
                        }
                    }
                }
            }
        }
        grid_sync(128);
    }
}

// ---------------- feed-forward GEMM v2: resident W + cp.async pipeline ----------
// 512 thr; CTA cols = 64 (NTN=4 per warp, wn 0..1); 256-row chunks looped.
// EPI: 1 = relu(+bias), 2 = +bias
#define FF_W_FLOATS (64*260)               /* 16640 */
#define FF_A_FLOATS (2*256*36)             /* 18432 */
#define FF_SMEM_BYTES ((FF_W_FLOATS + FF_A_FLOATS)*4)

template<int EPI>
__global__ void __launch_bounds__(512, 1)
gemm_ff2(const float* __restrict__ A, const float* __restrict__ W,
         const float* __restrict__ bias, float* __restrict__ out,
         int NC, int nrt)
{
    extern __shared__ float sm[];
    float* Ws = sm;
    float* As = sm + FF_W_FLOATS;
    const int tid = threadIdx.x, lane = tid & 31, wid = tid >> 5;
    const int wm = wid >> 1, wn = wid & 1;
    const int bcol = blockIdx.x;

    for (int i = tid; i < 64*H_DIM; i += 512){
        int c = i >> 8, k = i & 255;
        Ws[c*260 + k] = __uint_as_float(f2tf(W[(size_t)(bcol*64 + c)*H_DIM + k]));
    }
    __syncthreads();

    const int nch = (nrt - (int)blockIdx.y + (int)gridDim.y - 1) / (int)gridDim.y;
    if (nch <= 0) return;
    const int total = nch*8;

    auto stage = [&](int p){
        int ci = p >> 3, kb = p & 7, buf = p & 1;
        int rt = blockIdx.y + ci*gridDim.y;
        const float* src = A + (size_t)rt*256*H_DIM + kb*32;
        float* dst = As + buf*256*36;
        #pragma unroll
        for (int i = tid; i < 2048; i += 512){
            int r = i >> 3, q = (i & 7)*4;
            cp16(&dst[r*36 + q], src + (size_t)r*H_DIM + q);
        }
        cp_commit();
    };

    float acc[2][4][4];
    stage(0);
    for (int p = 0; p < total; p++){
        if (p + 1 < total){ stage(p + 1); cp_wait<1>(); }
        else cp_wait<0>();
        __syncthreads();
        const int kb = p & 7;
        if (kb == 0){
            #pragma unroll
            for (int a = 0; a < 2; a++)
                #pragma unroll
                for (int b = 0; b < 4; b++)
                    #pragma unroll
                    for (int c = 0; c < 4; c++) acc[a][b][c] = 0.f;
        }
        const float* Ab = As + (p & 1)*256*36;
        const int kbase = kb*32;
        #pragma unroll
        for (int kk = 0; kk < 32; kk += 8){
            uint32_t af[2][4];
            #pragma unroll
            for (int mt = 0; mt < 2; mt++){
                int r0 = wm*32 + mt*16 + (lane >> 2);
                int c0 = kk + (lane & 3);
                af[mt][0] = f2tf(Ab[r0*36 + c0]);
                af[mt][1] = f2tf(Ab[(r0+8)*36 + c0]);
                af[mt][2] = f2tf(Ab[r0*36 + c0 + 4]);
                af[mt][3] = f2tf(Ab[(r0+8)*36 + c0 + 4]);
            }
            uint32_t bf[4][2];
            #pragma unroll
            for (int nt = 0; nt < 4; nt++){
                int n0 = wn*32 + nt*8 + (lane >> 2);
                bf[nt][0] = __float_as_uint(Ws[n0*260 + kbase + kk + (lane & 3)]);
                bf[nt][1] = __float_as_uint(Ws[n0*260 + kbase + kk + 4 + (lane & 3)]);
            }
            #pragma unroll
            for (int mt = 0; mt < 2; mt++)
                #pragma unroll
                for (int nt = 0; nt < 4; nt++)
                    mma8(acc[mt][nt], af[mt], bf[nt]);
        }
        __syncthreads();

        if (kb == 7){
            int rt = blockIdx.y + (p >> 3)*gridDim.y;
            #pragma unroll
            for (int mt = 0; mt < 2; mt++){
                #pragma unroll
                for (int nt = 0; nt < 4; nt++){
                    #pragma unroll
                    for (int dr = 0; dr < 2; dr++){
                        int rr = rt*256 + wm*32 + mt*16 + (lane >> 2) + dr*8;
                        #pragma unroll
                        for (int dc = 0; dc < 2; dc++){
                            int cc = bcol*64 + wn*32 + nt*8 + (lane & 3)*2 + dc;
                            float v = acc[mt][nt][dr*2 + dc] + bias[cc];
                            if (EPI == 1) v = fmaxf(v, 0.f);
                            out[(size_t)rr*NC + cc] = v;
                        }
                    }
                }
            }
        }
    }
}

// ---------------- persistent main-loop GRU v3: cp.async flat pipeline -----------
#define MAIN_W_FLOATS (3*16*260)           /* 12480 */
#define MAIN_A_FLOATS (2*128*36)           /* 9216  */
#define MAIN_SMEM_BYTES ((MAIN_W_FLOATS + MAIN_A_FLOATS)*4)

__global__ void __launch_bounds__(256, 1)
main_gru_v3(const float* __restrict__ whh, const float* __restrict__ bhh,
            float* __restrict__ out)
{
    extern __shared__ float sm[];
    float* Ws = sm;
    float* As = sm + MAIN_W_FLOATS;
    const int tid = threadIdx.x, lane = tid & 31, wid = tid >> 5;
    const int wm = wid >> 1, wn = wid & 1;
    const int bcol = blockIdx.x;          // 0..15
    const int row0 = blockIdx.y*128;      // 0..7 *128

    for (int i = tid; i < 3*16*H_DIM; i += 256){
        int g = i >> 12, rem = i & 4095;
        int c = rem >> 8, k = rem & 255;
        Ws[(g*16 + c)*260 + k] =
            __uint_as_float(f2tf(whh[(size_t)(g*H_DIM + bcol*16 + c)*H_DIM + k]));
    }
    const int cb0 = bcol*16 + wn*8 + (lane & 3)*2;
    float bR0 = bhh[cb0],           bR1 = bhh[cb0 + 1];
    float bZ0 = bhh[H_DIM + cb0],   bZ1 = bhh[H_DIM + cb0 + 1];
    float bN0 = bhh[2*H_DIM + cb0], bN1 = bhh[2*H_DIM + cb0 + 1];
    __syncthreads();

    for (int t = 0; t < T_DIM; t++){
        const float* __restrict__ hsrc = g_hm[t & 1];
        float* __restrict__ hdst = g_hm[(t + 1) & 1];

        auto stage = [&](int p){
            int kb = p & 7, buf = p & 1;
            const float* src = hsrc + (size_t)row0*H_DIM + kb*32;
            float* dst = As + buf*128*36;
            #pragma unroll
            for (int i = tid; i < 1024; i += 256){
                int r = i >> 3, q = (i & 7)*4;
                cp16(&dst[r*36 + q], src + (size_t)r*H_DIM + q);
            }
            cp_commit();
        };

        float acc[3][2][4];
        #pragma unroll
        for (int g = 0; g < 3; g++)
            #pragma unroll
            for (int m = 0; m < 2; m++)
                #pragma unroll
                for (int c = 0; c < 4; c++) acc[g][m][c] = 0.f;

        stage(0);
        for (int p = 0; p < 8; p++){
            if (p + 1 < 8){ stage(p + 1); cp_wait<1>(); }
            else cp_wait<0>();
            __syncthreads();
            const float* Ab = As + (p & 1)*128*36;
            const int kbase = (p & 7)*32;
            #pragma unroll
            for (int kk = 0; kk < 32; kk += 8){
                uint32_t af[2][4];
                #pragma unroll
                for (int mt = 0; mt < 2; mt++){
                    int r0 = wm*32 + mt*16 + (lane >> 2);
                    int c0 = kk + (lane & 3);
                    af[mt][0] = f2tf(Ab[r0*36 + c0]);
                    af[mt][1] = f2tf(Ab[(r0+8)*36 + c0]);
                    af[mt][2] = f2tf(Ab[r0*36 + c0 + 4]);
                    af[mt][3] = f2tf(Ab[(r0+8)*36 + c0 + 4]);
                }
                uint32_t bf[3][2];
                int n0 = wn*8 + (lane >> 2);
                #pragma unroll
                for (int g = 0; g < 3; g++){
                    bf[g][0] = __float_as_uint(Ws[(g*16 + n0)*260 + kbase + kk + (lane & 3)]);
                    bf[g][1] = __float_as_uint(Ws[(g*16 + n0)*260 + kbase + kk + 4 + (lane & 3)]);
                }
                #pragma unroll
                for (int g = 0; g < 3; g++)
                    #pragma unroll
                    for (int mt = 0; mt < 2; mt++)
                        mma8(acc[g][mt], af[mt], bf[g]);
            }
            __syncthreads();
        }

        const float* __restrict__ gi_t = g_GI + (size_t)t*N_DIM*G3;
        float* __restrict__ out_t = out + ((size_t)t*N_DIM)*ROW_OUT;
        #pragma unroll
        for (int mt = 0; mt < 2; mt++){
            #pragma unroll
            for (int dr = 0; dr < 2; dr++){
                int row = row0 + wm*32 + mt*16 + (lane >> 2) + dr*8;
                const float* gi = gi_t + (size_t)row*G3;
                #pragma unroll
                for (int dc = 0; dc < 2; dc++){
                    int c = cb0 + dc;
                    float gr = acc[0][mt][dr*2+dc] + (dc ? bR1 : bR0);
                    float gz = acc[1][mt][dr*2+dc] + (dc ? bZ1 : bZ0);
                    float gn = acc[2][mt][dr*2+dc] + (dc ? bN1 : bN0);
                    float r  = sigm(__ldg(&gi[c]) + gr);
                    float z  = sigm(__ldg(&gi[H_DIM + c]) + gz);
                    float nn = tanhf(__ldg(&gi[2*H_DIM + c]) + r*gn);
                    float hold = __ldcg(&hsrc[(size_t)row*H_DIM + c]);
                    float hnew = (1.f - z)*nn + z*hold;
                    __stcg(&hdst[(size_t)row*H_DIM + c], hnew);
                    out_t[(size_t)row*ROW_OUT + 4 + c] = hnew;
                }
            }
        }
        grid_sync(128);
    }
}

// ---------------- heads ----------------
__global__ void __launch_bounds__(256)
heads_kernel(float* __restrict__ out, const int* __restrict__ actions,
             const int* __restrict__ active, const float* __restrict__ p0,
             const float* __restrict__ pp0,
             const float* __restrict__ w_actor, const float* __restrict__ b_actor,
             const float* __restrict__ w_critic, const float* __restrict__ b_critic)
{
    int wid = threadIdx.x >> 5, lane = threadIdx.x & 31;
    size_t row = (size_t)blockIdx.x*8 + wid;
    float* orow = out + row*ROW_OUT;
    float hv[8];
    #pragma unroll
    for (int i = 0; i < 8; i++) hv[i] = orow[4 + lane + 32*i];

    float lg = 0.f;
    #pragma unroll
    for (int a = 0; a < NA_DIM; a++){
        float s = 0.f;
        #pragma unroll
        for (int i = 0; i < 8; i++) s += hv[i]*w_actor[a*H_DIM + lane + 32*i];
        #pragma unroll
        for (int o = 16; o > 0; o >>= 1) s += __shfl_xor_sync(0xffffffffu, s, o);
        if (lane == a) lg = s + b_actor[a];
    }
    float m = (lane < NA_DIM) ? lg : -1e30f;
    #pragma unroll
    for (int o = 16; o > 0; o >>= 1) m = fmaxf(m, __shfl_xor_sync(0xffffffffu, m, o));
    float e = (lane < NA_DIM) ? expf(lg - m) : 0.f;
    float den = e;
    #pragma unroll
    for (int o = 16; o > 0; o >>= 1) den += __shfl_xor_sync(0xffffffffu, den, o);
    if (lane < NA_DIM) orow[260 + lane] = e/den;

    float s = 0.f;
    #pragma unroll
    for (int i = 0; i < 8; i++) s += hv[i]*w_critic[lane + 32*i];
    #pragma unroll
    for (int o = 16; o > 0; o >>= 1) s += __shfl_xor_sync(0xffffffffu, s, o);

    int n = (int)(row & (N_DIM - 1));
    if (lane == 0)  orow[3]   = s + b_critic[0];
    if (lane == 16) orow[0]   = (float)actions[row];
    if (lane == 17) orow[1]   = p0[n];
    if (lane == 18) orow[2]   = (float)active[row];
    if (lane == 19) orow[276] = pp0[n*2];
    if (lane == 20) orow[277] = pp0[n*2 + 1];
}

// ---------------- launch ----------------
extern "C" void kernel_launch(void* const* d_in, const int* in_sizes, int n_in,
                              void* d_out, int out_size)
{
    (void)in_sizes; (void)n_in; (void)out_size;
    const float* condition = (const float*)d_in[0];
    const int*   active    = (const int*)d_in[1];
    const int*   lines     = (const int*)d_in[2];
    const int*   actions   = (const int*)d_in[3];
    const float* h0        = (const float*)d_in[4];
    const float* p0        = (const float*)d_in[5];
    const float* pp0       = (const float*)d_in[6];
    const float* embed     = (const float*)d_in[7];
    const float* wih_f = (const float*)d_in[8],  *whh_f = (const float*)d_in[9];
    const float* bih_f = (const float*)d_in[10], *bhh_f = (const float*)d_in[11];
    const float* wih_b = (const float*)d_in[12], *whh_b = (const float*)d_in[13];
    const float* bih_b = (const float*)d_in[14], *bhh_b = (const float*)d_in[15];
    const float* f_w0 = (const float*)d_in[16], *f_b0 = (const float*)d_in[17];
    const float* f_w1 = (const float*)d_in[18], *f_b1 = (const float*)d_in[19];
    const float* f_w2 = (const float*)d_in[20], *f_b2 = (const float*)d_in[21];
    const float* c_wih = (const float*)d_in[22], *c_whh = (const float*)d_in[23];
    const float* c_bih = (const float*)d_in[24], *c_bhh = (const float*)d_in[25];
    const float* w_critic = (const float*)d_in[26], *b_critic = (const float*)d_in[27];
    const float* w_actor  = (const float*)d_in[28], *b_actor  = (const float*)d_in[29];
    float* out = (float*)d_out;

    float *A0p, *A1p, *Rp, *GIp;
    cudaGetSymbolAddress((void**)&A0p, g_A0);
    cudaGetSymbolAddress((void**)&A1p, g_A1);
    cudaGetSymbolAddress((void**)&Rp,  g_Rproj);
    cudaGetSymbolAddress((void**)&GIp, g_GI);

    cudaFuncSetAttribute(enc_v2,
                         cudaFuncAttributeMaxDynamicSharedMemorySize, ENC_SMEM_BYTES);
    cudaFuncSetAttribute(main_gru_v3,
                         cudaFuncAttributeMaxDynamicSharedMemorySize, MAIN_SMEM_BYTES);
    cudaFuncSetAttribute(gemm_ff2<1>,
                         cudaFuncAttributeMaxDynamicSharedMemorySize, FF_SMEM_BYTES);
    cudaFuncSetAttribute(gemm_ff2<2>,
                         cudaFuncAttributeMaxDynamicSharedMemorySize, FF_SMEM_BYTES);

    // 0) gi tables + state init
    gi_tables<<<(2*NL_DIM*G3 + 255)/256, 256>>>(embed, wih_f, bih_f, wih_b, bih_b);
    init_state<<<4096, 256>>>(h0);

    // 1) persistent bidirectional encoder
    enc_v2<<<dim3(8, 16), 512, ENC_SMEM_BYTES>>>(whh_f, bhh_f, whh_b, bhh_b, lines);

    // 2) Rproj = Hmem @ W0r^T (dedup over (w,n))
    gemm_plain<1, 0><<<dim3(4, 128), 256>>>(nullptr, f_w0 + 64, 576, nullptr, Rp, 512, 256, nullptr);
    // 3) A0 = relu(cond @ W0c^T + Rproj[active] + b0)
    gemm_plain<0, 3><<<dim3(4, 2048), 256>>>(condition, f_w0, 576, f_b0, A0p, 64, 256, active);
    // 4) A1 = relu(A0 @ w1^T + b1); A0 = relu(A1 @ w2^T + b2)
    gemm_ff2<1><<<dim3(4, 33), 512, FF_SMEM_BYTES>>>(A0p, f_w1, f_b1, A1p, 256, 1024);
    gemm_ff2<1><<<dim3(4, 33), 512, FF_SMEM_BYTES>>>(A1p, f_w2, f_b2, A0p, 256, 1024);
    // 5) GI = A0 @ c_wih^T + c_bih
    gemm_ff2<2><<<dim3(12, 11), 512, FF_SMEM_BYTES>>>(A0p, c_wih, c_bih, GIp, 768, 1024);

    // 6) persistent main GRU
    main_gru_v3<<<dim3(16, 8), 256, MAIN_SMEM_BYTES>>>(c_whh, c_bhh, out);

    // 7) heads + scalar fields
    heads_kernel<<<TN/8, 256>>>(out, actions, active, p0, pp0,
                                w_actor, b_actor, w_critic, b_critic);
}